// round 10
// baseline (speedup 1.0000x reference)
#include <cuda_runtime.h>
#include <cuda_bf16.h>
#include <math.h>
#include <stdint.h>

// Problem constants
#define BATCH 2
#define SEQ   2048
#define EMB   2048
#define NHEAD 16
#define NGRP  4
#define HDIM  128
#define FFN   8192
#define TOK   (BATCH*SEQ)          // 4096 rows
#define KVW   (NGRP*HDIM)          // 512

typedef __nv_bfloat16 bf16;

// ---------------------------------------------------------------------------
// PTX helpers (portable sm_80+: cp.async / ldmatrix / mma.sync)
// ---------------------------------------------------------------------------
__device__ __forceinline__ uint32_t smem_to_u32(const void* smem_ptr) {
    uint32_t addr;
    asm("{ .reg .u64 tmp; cvta.to.shared.u64 tmp, %1; cvt.u32.u64 %0, tmp; }"
        : "=r"(addr) : "l"(smem_ptr));
    return addr;
}

#define CP_ASYNC16(dst, src) \
    asm volatile("cp.async.cg.shared.global [%0], [%1], 16;\n" \
                 :: "r"(dst), "l"(src))
#define CP_COMMIT() asm volatile("cp.async.commit_group;\n" ::: "memory")
#define CP_WAIT(N)  asm volatile("cp.async.wait_group %0;\n" :: "n"(N) : "memory")

__device__ __forceinline__ void ldsm_x4(uint32_t* r, uint32_t addr) {
    asm volatile("ldmatrix.sync.aligned.m8n8.x4.shared.b16 {%0,%1,%2,%3}, [%4];\n"
        : "=r"(r[0]), "=r"(r[1]), "=r"(r[2]), "=r"(r[3]) : "r"(addr));
}

__device__ __forceinline__ void ldsm_x4_t(uint32_t* r, uint32_t addr) {
    asm volatile("ldmatrix.sync.aligned.m8n8.x4.trans.shared.b16 {%0,%1,%2,%3}, [%4];\n"
        : "=r"(r[0]), "=r"(r[1]), "=r"(r[2]), "=r"(r[3]) : "r"(addr));
}

__device__ __forceinline__ void mma_bf16(float* c, const uint32_t* a, const uint32_t* b) {
    asm volatile(
        "mma.sync.aligned.m16n8k16.row.col.f32.bf16.bf16.f32 "
        "{%0,%1,%2,%3}, {%4,%5,%6,%7}, {%8,%9}, {%0,%1,%2,%3};\n"
        : "+f"(c[0]), "+f"(c[1]), "+f"(c[2]), "+f"(c[3])
        : "r"(a[0]), "r"(a[1]), "r"(a[2]), "r"(a[3]), "r"(b[0]), "r"(b[1]));
}

__device__ __forceinline__ void split2(float v, bf16& h, bf16& l) {
    h = __float2bfloat16(v);
    l = __float2bfloat16(v - __bfloat162float(h));
}

// pack float pair -> (hi bf162, lo bf162) as uint32
__device__ __forceinline__ void split_pair(float a, float b, uint32_t& hu, uint32_t& lu) {
    __nv_bfloat162 h = __float22bfloat162_rn(make_float2(a, b));
    float2 back = __bfloat1622float2(h);
    __nv_bfloat162 l = __float22bfloat162_rn(make_float2(a - back.x, b - back.y));
    hu = *reinterpret_cast<uint32_t*>(&h);
    lu = *reinterpret_cast<uint32_t*>(&l);
}

__device__ __forceinline__ float gelu_exact(float a) {
    return 0.5f * a * (1.0f + erff(a * 0.70710678118654752f));
}

// ---------------------------------------------------------------------------
// Scratch (device globals; allocation-free per harness rules)
// ---------------------------------------------------------------------------
__device__ __align__(256) bf16 g_xrot_hi[TOK*EMB];
__device__ __align__(256) bf16 g_xrot_lo[TOK*EMB];
__device__ __align__(256) bf16 g_x_hi[TOK*EMB];
__device__ __align__(256) bf16 g_x_lo[TOK*EMB];
__device__ __align__(256) bf16 g_q_hi[TOK*EMB];
__device__ __align__(256) bf16 g_q_lo[TOK*EMB];
__device__ __align__(256) bf16 g_k_hi[TOK*KVW];
__device__ __align__(256) bf16 g_k_lo[TOK*KVW];
__device__ __align__(256) bf16 g_v_hi[TOK*KVW];
__device__ __align__(256) bf16 g_v_lo[TOK*KVW];
__device__ __align__(256) bf16 g_ctx_hi[TOK*EMB];
__device__ __align__(256) bf16 g_ctx_lo[TOK*EMB];
__device__ __align__(256) float g_attn[TOK*EMB];
__device__ __align__(256) float g_h[TOK*EMB];
__device__ __align__(256) bf16 g_h_hi[TOK*EMB];
__device__ __align__(256) bf16 g_h_lo[TOK*EMB];
__device__ __align__(256) bf16 g_act_hi[(size_t)TOK*FFN];
__device__ __align__(256) bf16 g_act_lo[(size_t)TOK*FFN];
__device__ __align__(256) float g_fc[TOK*EMB];
// transposed weights (B^T layout [N][K]), split
__device__ __align__(256) bf16 g_wqT_hi[EMB*EMB];
__device__ __align__(256) bf16 g_wqT_lo[EMB*EMB];
__device__ __align__(256) bf16 g_wkT_hi[KVW*EMB];
__device__ __align__(256) bf16 g_wkT_lo[KVW*EMB];
__device__ __align__(256) bf16 g_wvT_hi[KVW*EMB];
__device__ __align__(256) bf16 g_wvT_lo[KVW*EMB];
__device__ __align__(256) bf16 g_woT_hi[EMB*EMB];
__device__ __align__(256) bf16 g_woT_lo[EMB*EMB];
__device__ __align__(256) bf16 g_winT_hi[(size_t)2*FFN*EMB];
__device__ __align__(256) bf16 g_winT_lo[(size_t)2*FFN*EMB];
__device__ __align__(256) bf16 g_woutT_hi[(size_t)EMB*FFN];
__device__ __align__(256) bf16 g_woutT_lo[(size_t)EMB*FFN];

// ---------------------------------------------------------------------------
// Transpose + split; optional row-interleave for GeGLU pairing:
// ilv_half>0 -> out row r' = (r < ilv_half) ? 2r : 2(r-ilv_half)+1
// ---------------------------------------------------------------------------
__global__ __launch_bounds__(256) void transpose_split_kernel(
        const float* __restrict__ in, bf16* __restrict__ hi, bf16* __restrict__ lo,
        int R, int C, int ilv_half) {
    __shared__ float t[32][33];
    int bx = blockIdx.x * 32, by = blockIdx.y * 32;
    int tx = threadIdx.x & 31, ty = threadIdx.x >> 5;
    #pragma unroll
    for (int i = ty; i < 32; i += 8)
        t[i][tx] = in[(size_t)(by + i) * C + bx + tx];
    __syncthreads();
    #pragma unroll
    for (int i = ty; i < 32; i += 8) {
        float v = t[tx][i];
        bf16 h, l; split2(v, h, l);
        size_t r = (size_t)(bx + i);
        if (ilv_half) r = (r < (size_t)ilv_half) ? 2*r : 2*(r - ilv_half) + 1;
        size_t o = r * R + by + tx;
        hi[o] = h; lo[o] = l;
    }
}

__global__ __launch_bounds__(256) void split_kernel(const float* __restrict__ in,
                                                    bf16* __restrict__ hi,
                                                    bf16* __restrict__ lo, size_t n) {
    size_t idx = (size_t)blockIdx.x * 256 + threadIdx.x;
    if (idx >= n) return;
    bf16 h, l; split2(in[idx], h, l);
    hi[idx] = h; lo[idx] = l;
}

// ---------------------------------------------------------------------------
// RoPE -> split bf16 pair
// ---------------------------------------------------------------------------
__global__ __launch_bounds__(256) void rope_split_kernel(const float* __restrict__ x,
                                                         bf16* __restrict__ hi,
                                                         bf16* __restrict__ lo) {
    int idx = blockIdx.x * 256 + threadIdx.x;
    if (idx >= TOK*EMB) return;
    int t = idx / EMB;
    int e = idx % EMB;
    int n = t % SEQ;
    int d = e % HDIM;
    int j; float partner; float sign;
    if (d < 64) { j = d;      partner = x[idx + 64]; sign = -1.f; }
    else        { j = d - 64; partner = x[idx - 64]; sign =  1.f; }
    float invf = powf(10000.0f, -(float)j / 64.0f);
    float ang = (float)n * invf;
    float c = cosf(ang), s = sinf(ang);
    float v = x[idx] * c + sign * partner * s;
    bf16 h, l; split2(v, h, l);
    hi[idx] = h; lo[idx] = l;
}

// ---------------------------------------------------------------------------
// bf16-split tensor-core GEMM: C = A @ BT^T.  128x128 tile, Kstep 32, 8 warps,
// 3-stage cp.async pipeline (overlap depth 2).  mode: 0 = fp32 C;
// 1 = bf16 hi/lo split to Ch/Cl; 2 = GeGLU epilogue -> bf16 hi/lo width N/2.
// ---------------------------------------------------------------------------
#define WST_B    80
#define OP_BYTES (128*WST_B)
#define STAGE_B  (4*OP_BYTES)
#define MG_SMEM  (3*STAGE_B)     // 122880

__global__ __launch_bounds__(256) void mma_gemm(
        const bf16* __restrict__ Ahi, const bf16* __restrict__ Alo,
        const bf16* __restrict__ Bhi, const bf16* __restrict__ Blo,
        float* __restrict__ C, bf16* __restrict__ Ch, bf16* __restrict__ Cl,
        int M, int N, int K, int mode) {
    extern __shared__ char smem[];
    const uint32_t sb = smem_to_u32(smem);
    const int tid = threadIdx.x;
    const int m0 = blockIdx.x * 128, n0 = blockIdx.y * 128;
    const int warp = tid >> 5, lane = tid & 31;
    const int wm = warp & 1, wn = warp >> 1;

    const bf16* srcs[4] = { Ahi + (size_t)m0 * K, Alo + (size_t)m0 * K,
                            Bhi + (size_t)n0 * K, Blo + (size_t)n0 * K };

    float acc[4][4][4];
    #pragma unroll
    for (int i = 0; i < 4; i++)
        #pragma unroll
        for (int j = 0; j < 4; j++)
            #pragma unroll
            for (int r = 0; r < 4; r++) acc[i][j][r] = 0.f;

    const int S = K >> 5;
    const int lA_row = lane & 15, lA_k = lane >> 4;
    const int lB_row = ((lane >> 4) << 3) + (lane & 7);
    const int lB_k = (lane >> 3) & 1;

    // stage loader: stage s -> buffer s%3
    auto issue_stage = [&](int s) {
        const uint32_t bufb = sb + (uint32_t)(s % 3) * STAGE_B;
        const int k0 = s << 5;
        #pragma unroll
        for (int it = 0; it < 8; it++) {
            int idx = tid + (it << 8);
            int op = it >> 1;
            int j = idx & 511;
            int row = j >> 2, ch = j & 3;
            const bf16* src = srcs[op] + (size_t)row * K + k0 + ch * 8;
            uint32_t dst = bufb + (uint32_t)(op * OP_BYTES + row * WST_B + ch * 16);
            CP_ASYNC16(dst, src);
        }
    };

    issue_stage(0); CP_COMMIT();
    if (S > 1) { issue_stage(1); CP_COMMIT(); }

    for (int s = 0; s < S; s++) {
        if (s + 1 < S) { CP_WAIT(1); } else { CP_WAIT(0); }
        __syncthreads();   // stage s visible to all; buffer (s+2)%3 reads done
        if (s + 2 < S) { issue_stage(s + 2); CP_COMMIT(); }

        const uint32_t base = sb + (uint32_t)(s % 3) * STAGE_B;
        #pragma unroll
        for (int k16 = 0; k16 < 2; k16++) {
            uint32_t ah[4][4], al[4][4], bh[4][2], bl[4][2];
            #pragma unroll
            for (int mt = 0; mt < 4; mt++) {
                uint32_t ra = base + (uint32_t)((wm * 64 + mt * 16 + lA_row) * WST_B)
                            + k16 * 32 + lA_k * 16;
                ldsm_x4(ah[mt], ra);
                ldsm_x4(al[mt], ra + OP_BYTES);
            }
            #pragma unroll
            for (int np = 0; np < 2; np++) {
                uint32_t rb = base + 2 * OP_BYTES
                            + (uint32_t)((wn * 32 + np * 16 + lB_row) * WST_B)
                            + k16 * 32 + lB_k * 16;
                uint32_t t4[4];
                ldsm_x4(t4, rb);
                bh[np*2][0] = t4[0]; bh[np*2][1] = t4[1];
                bh[np*2+1][0] = t4[2]; bh[np*2+1][1] = t4[3];
                ldsm_x4(t4, rb + OP_BYTES);
                bl[np*2][0] = t4[0]; bl[np*2][1] = t4[1];
                bl[np*2+1][0] = t4[2]; bl[np*2+1][1] = t4[3];
            }
            #pragma unroll
            for (int mt = 0; mt < 4; mt++)
                #pragma unroll
                for (int nt = 0; nt < 4; nt++) {
                    mma_bf16(acc[mt][nt], ah[mt], bh[nt]);
                    mma_bf16(acc[mt][nt], ah[mt], bl[nt]);
                    mma_bf16(acc[mt][nt], al[mt], bh[nt]);
                }
        }
        __syncthreads();   // all warps done with buffer s%3 before it's refilled
    }

    #pragma unroll
    for (int mt = 0; mt < 4; mt++) {
        int m = m0 + wm * 64 + mt * 16 + (lane >> 2);
        #pragma unroll
        for (int nt = 0; nt < 4; nt++) {
            int n = n0 + wn * 32 + nt * 8 + 2 * (lane & 3);
            if (mode == 0) {
                *(float2*)(C + (size_t)m * N + n) =
                    make_float2(acc[mt][nt][0], acc[mt][nt][1]);
                *(float2*)(C + (size_t)(m + 8) * N + n) =
                    make_float2(acc[mt][nt][2], acc[mt][nt][3]);
            } else if (mode == 1) {
                uint32_t hu, lu;
                split_pair(acc[mt][nt][0], acc[mt][nt][1], hu, lu);
                *(uint32_t*)(Ch + (size_t)m * N + n) = hu;
                *(uint32_t*)(Cl + (size_t)m * N + n) = lu;
                split_pair(acc[mt][nt][2], acc[mt][nt][3], hu, lu);
                *(uint32_t*)(Ch + (size_t)(m + 8) * N + n) = hu;
                *(uint32_t*)(Cl + (size_t)(m + 8) * N + n) = lu;
            } else {
                // GeGLU: (c0,c1)=(a,g) for row m; (c2,c3) for row m+8
                int Nh = N >> 1;
                int f = n >> 1;
                float v0 = gelu_exact(acc[mt][nt][0]) * acc[mt][nt][1];
                float v1 = gelu_exact(acc[mt][nt][2]) * acc[mt][nt][3];
                bf16 h0, l0, h1, l1;
                split2(v0, h0, l0);
                split2(v1, h1, l1);
                Ch[(size_t)m * Nh + f] = h0;       Cl[(size_t)m * Nh + f] = l0;
                Ch[(size_t)(m + 8) * Nh + f] = h1; Cl[(size_t)(m + 8) * Nh + f] = l1;
            }
        }
    }
}

// ---------------------------------------------------------------------------
// Tensor-core flash attention (bf16 split, causal, GQA)
// CTA: 128 q-rows, iterate 64-kv tiles.  8 warps, warp = 16 q-rows x all 64 kv.
// Q [128][272B] hi/lo resident; K,V [64][272B] hi/lo, 2-stage cp.async ring.
// V stored row-major [kv][d]; P@V B-operands via ldmatrix.trans.
// ---------------------------------------------------------------------------
#define FSQ_H  0
#define FSQ_L  34816
#define FST0   69632
#define FSTAGE 69632          // per-stage: KH,KL,VH,VL each 64*272=17408
#define FKL_OFF 17408
#define FVH_OFF 34816
#define FVL_OFF 52224
#define FL_SMEM (FST0 + 2*FSTAGE)   // 208896

__global__ __launch_bounds__(256) void flash_mma_kernel(
        const bf16* __restrict__ Qh, const bf16* __restrict__ Ql,
        const bf16* __restrict__ Kh, const bf16* __restrict__ Kl,
        const bf16* __restrict__ Vh, const bf16* __restrict__ Vl,
        bf16* __restrict__ Oh, bf16* __restrict__ Ol) {
    extern __shared__ char smem[];
    const uint32_t sb = smem_to_u32(smem);
    const int qt = (int)gridDim.x - 1 - (int)blockIdx.x;  // big tiles first
    const int hd = blockIdx.y, b = blockIdx.z;
    const int g = hd / (NHEAD / NGRP);
    const int tid = threadIdx.x;
    const int warp = tid >> 5, lane = tid & 31;
    const int lA_row = lane & 15, lA_k = lane >> 4;
    const int lB_row = ((lane >> 4) << 3) + (lane & 7);
    const int lB_k = (lane >> 3) & 1;
    const float SC = 0.08838834764831845f * 1.4426950408889634f;  // scale*log2e

    // load Q tile (128 x 128 bf16, hi+lo) — plain vector stores, synced below
    {
        const size_t qbase = ((size_t)(b * SEQ + qt * 128)) * EMB + hd * HDIM;
        #pragma unroll
        for (int it = 0; it < 8; it++) {
            int i = tid + (it << 8);       // 0..2047
            int row = i >> 4, ch = i & 15;
            size_t ga = qbase + (size_t)row * EMB + ch * 8;
            *(uint4*)(smem + FSQ_H + row * 272 + ch * 16) = *(const uint4*)(Qh + ga);
            *(uint4*)(smem + FSQ_L + row * 272 + ch * 16) = *(const uint4*)(Ql + ga);
        }
    }

    // K/V stage loader (cp.async, 16 chunks per thread)
    auto issue_kv = [&](int kt) {
        const uint32_t stb = sb + FST0 + (uint32_t)(kt & 1) * FSTAGE;
        const size_t kbase = ((size_t)(b * SEQ + kt * 64)) * KVW + g * HDIM;
        const bf16* gsrc[4] = { Kh + kbase, Kl + kbase, Vh + kbase, Vl + kbase };
        #pragma unroll
        for (int it = 0; it < 16; it++) {
            int idx = tid + (it << 8);
            int arr = it >> 2;              // 1024 chunks per array
            int j = idx & 1023;
            int row = j >> 4, ch = j & 15;
            const bf16* src = gsrc[arr] + (size_t)row * KVW + ch * 8;
            uint32_t dst = stb + (uint32_t)arr * 17408u + (uint32_t)(row * 272 + ch * 16);
            CP_ASYNC16(dst, src);
        }
    };

    float o[16][4];
    #pragma unroll
    for (int i = 0; i < 16; i++)
        #pragma unroll
        for (int r = 0; r < 4; r++) o[i][r] = 0.f;
    float m0 = -1e30f, m1 = -1e30f, l0 = 0.f, l1 = 0.f;

    const int qg0 = qt * 128 + warp * 16 + (lane >> 2);
    const int qg1 = qg0 + 8;
    const int NT = 2 * qt + 2;

    issue_kv(0);
    CP_COMMIT();

    for (int kt = 0; kt < NT; kt++) {
        if (kt + 1 < NT) {
            issue_kv(kt + 1);   // writes buf (kt+1)&1, last read at kt-1 (synced)
            CP_COMMIT();
            CP_WAIT(1);
        } else {
            CP_WAIT(0);
        }
        __syncthreads();
        const uint32_t stb = sb + FST0 + (uint32_t)(kt & 1) * FSTAGE;

        // --- S = Q @ K^T (3-MMA split) ---
        float s[8][4];
        #pragma unroll
        for (int j = 0; j < 8; j++)
            #pragma unroll
            for (int r = 0; r < 4; r++) s[j][r] = 0.f;

        #pragma unroll
        for (int ks = 0; ks < 8; ks++) {
            uint32_t qh4[4], ql4[4];
            uint32_t ra = sb + FSQ_H + (uint32_t)((warp * 16 + lA_row) * 272)
                        + ks * 32 + lA_k * 16;
            ldsm_x4(qh4, ra);
            ldsm_x4(ql4, ra + (FSQ_L - FSQ_H));
            #pragma unroll
            for (int np = 0; np < 4; np++) {
                uint32_t th[4], tl[4];
                uint32_t rb = stb + (uint32_t)((np * 16 + lB_row) * 272)
                            + ks * 32 + lB_k * 16;
                ldsm_x4(th, rb);
                ldsm_x4(tl, rb + FKL_OFF);
                uint32_t bh0[2] = {th[0], th[1]}, bh1[2] = {th[2], th[3]};
                uint32_t bl0[2] = {tl[0], tl[1]}, bl1[2] = {tl[2], tl[3]};
                mma_bf16(s[2*np],   qh4, bh0);
                mma_bf16(s[2*np],   qh4, bl0);
                mma_bf16(s[2*np],   ql4, bh0);
                mma_bf16(s[2*np+1], qh4, bh1);
                mma_bf16(s[2*np+1], qh4, bl1);
                mma_bf16(s[2*np+1], ql4, bh1);
            }
        }

        // --- online softmax (raw-score max; mask by zeroing p) ---
        float tm0 = -1e30f, tm1 = -1e30f;
        #pragma unroll
        for (int j = 0; j < 8; j++) {
            tm0 = fmaxf(tm0, fmaxf(s[j][0], s[j][1]));
            tm1 = fmaxf(tm1, fmaxf(s[j][2], s[j][3]));
        }
        tm0 = fmaxf(tm0, __shfl_xor_sync(0xffffffffu, tm0, 1));
        tm0 = fmaxf(tm0, __shfl_xor_sync(0xffffffffu, tm0, 2));
        tm1 = fmaxf(tm1, __shfl_xor_sync(0xffffffffu, tm1, 1));
        tm1 = fmaxf(tm1, __shfl_xor_sync(0xffffffffu, tm1, 2));
        float m0n = fmaxf(m0, tm0), m1n = fmaxf(m1, tm1);
        float c0 = exp2f((m0 - m0n) * SC), c1 = exp2f((m1 - m1n) * SC);

        const bool domask = (kt >= 2 * qt);
        float l0a = 0.f, l1a = 0.f;
        #pragma unroll
        for (int j = 0; j < 8; j++) {
            float p0 = exp2f((s[j][0] - m0n) * SC);
            float p1 = exp2f((s[j][1] - m0n) * SC);
            float p2 = exp2f((s[j][2] - m1n) * SC);
            float p3 = exp2f((s[j][3] - m1n) * SC);
            if (domask) {
                int colb = kt * 64 + j * 8 + 2 * (lane & 3);
                if (colb     > qg0) p0 = 0.f;
                if (colb + 1 > qg0) p1 = 0.f;
                if (colb     > qg1) p2 = 0.f;
                if (colb + 1 > qg1) p3 = 0.f;
            }
            s[j][0] = p0; s[j][1] = p1; s[j][2] = p2; s[j][3] = p3;
            l0a += p0 + p1; l1a += p2 + p3;
        }
        l0a += __shfl_xor_sync(0xffffffffu, l0a, 1);
        l0a += __shfl_xor_sync(0xffffffffu, l0a, 2);
        l1a += __shfl_xor_sync(0xffffffffu, l1a, 1);
        l1a += __shfl_xor_sync(0xffffffffu, l1a, 2);
        l0 = l0 * c0 + l0a;
        l1 = l1 * c1 + l1a;
        m0 = m0n; m1 = m1n;

        #pragma unroll
        for (int i = 0; i < 16; i++) {
            o[i][0] *= c0; o[i][1] *= c0; o[i][2] *= c1; o[i][3] *= c1;
        }

        // --- O += P @ V (3-MMA split; V [kv][d] via ldmatrix.trans) ---
        #pragma unroll
        for (int ks = 0; ks < 4; ks++) {
            uint32_t ah[4], al[4];
            split_pair(s[2*ks][0],   s[2*ks][1],   ah[0], al[0]);
            split_pair(s[2*ks][2],   s[2*ks][3],   ah[1], al[1]);
            split_pair(s[2*ks+1][0], s[2*ks+1][1], ah[2], al[2]);
            split_pair(s[2*ks+1][2], s[2*ks+1][3], ah[3], al[3]);
            #pragma unroll
            for (int dp = 0; dp < 8; dp++) {
                uint32_t th[4], tl[4];
                uint32_t rb = stb + FVH_OFF
                            + (uint32_t)((ks * 16 + (lane & 15)) * 272)
                            + (uint32_t)((dp * 16 + ((lane >> 4) << 3)) * 2);
                ldsm_x4_t(th, rb);
                ldsm_x4_t(tl, rb + (FVL_OFF - FVH_OFF));
                uint32_t bh0[2] = {th[0], th[1]}, bh1[2] = {th[2], th[3]};
                uint32_t bl0[2] = {tl[0], tl[1]}, bl1[2] = {tl[2], tl[3]};
                mma_bf16(o[2*dp],   ah, bh0);
                mma_bf16(o[2*dp],   ah, bl0);
                mma_bf16(o[2*dp],   al, bh0);
                mma_bf16(o[2*dp+1], ah, bh1);
                mma_bf16(o[2*dp+1], ah, bl1);
                mma_bf16(o[2*dp+1], al, bh1);
            }
        }
        __syncthreads();   // all warps done reading stage kt&1 before overwrite
    }

    // epilogue: divide by l, write ctx hi/lo
    float inv0 = 1.f / l0, inv1 = 1.f / l1;
    const size_t tok0 = (size_t)(b * SEQ + qt * 128 + warp * 16 + (lane >> 2));
    #pragma unroll
    for (int dt = 0; dt < 16; dt++) {
        int col = hd * HDIM + dt * 8 + 2 * (lane & 3);
        uint32_t hu, lu;
        split_pair(o[dt][0] * inv0, o[dt][1] * inv0, hu, lu);
        *(uint32_t*)(Oh + tok0 * EMB + col) = hu;
        *(uint32_t*)(Ol + tok0 * EMB + col) = lu;
        split_pair(o[dt][2] * inv1, o[dt][3] * inv1, hu, lu);
        *(uint32_t*)(Oh + (tok0 + 8) * EMB + col) = hu;
        *(uint32_t*)(Ol + (tok0 + 8) * EMB + col) = lu;
    }
}

// ---------------------------------------------------------------------------
// out = rmsnorm(a + b) * w ; optional split outputs
// ---------------------------------------------------------------------------
__global__ __launch_bounds__(256) void add_rmsnorm_kernel(const float* __restrict__ a,
                                                          const float* __restrict__ b,
                                                          const float* __restrict__ w,
                                                          float* __restrict__ out,
                                                          bf16* __restrict__ oh,
                                                          bf16* __restrict__ ol) {
    int row = blockIdx.x;
    const float4* a4 = (const float4*)(a + (size_t)row * EMB);
    const float4* b4 = (const float4*)(b + (size_t)row * EMB);
    const float4* w4 = (const float4*)w;
    float4* o4 = (float4*)(out + (size_t)row * EMB);

    float4 s[2];
    float ss = 0.f;
    #pragma unroll
    for (int i = 0; i < 2; i++) {
        float4 av = a4[threadIdx.x + i * 256];
        float4 bv = b4[threadIdx.x + i * 256];
        s[i] = make_float4(av.x + bv.x, av.y + bv.y, av.z + bv.z, av.w + bv.w);
        ss += s[i].x * s[i].x + s[i].y * s[i].y + s[i].z * s[i].z + s[i].w * s[i].w;
    }
    __shared__ float red[8];
    for (int o = 16; o > 0; o >>= 1) ss += __shfl_xor_sync(0xffffffff, ss, o);
    if ((threadIdx.x & 31) == 0) red[threadIdx.x >> 5] = ss;
    __syncthreads();
    __shared__ float total_s;
    if (threadIdx.x == 0) {
        float t = 0.f;
        #pragma unroll
        for (int i = 0; i < 8; i++) t += red[i];
        total_s = t;
    }
    __syncthreads();
    float rstd = rsqrtf(total_s / (float)EMB + 1e-6f);
    #pragma unroll
    for (int i = 0; i < 2; i++) {
        float4 wv = w4[threadIdx.x + i * 256];
        float4 ov = make_float4(s[i].x * rstd * wv.x, s[i].y * rstd * wv.y,
                                s[i].z * rstd * wv.z, s[i].w * rstd * wv.w);
        o4[threadIdx.x + i * 256] = ov;
        if (oh) {
            size_t base = (size_t)row * EMB + (threadIdx.x + i * 256) * 4;
            uint32_t hu, lu;
            split_pair(ov.x, ov.y, hu, lu);
            *(uint32_t*)(oh + base) = hu; *(uint32_t*)(ol + base) = lu;
            split_pair(ov.z, ov.w, hu, lu);
            *(uint32_t*)(oh + base + 2) = hu; *(uint32_t*)(ol + base + 2) = lu;
        }
    }
}

// ---------------------------------------------------------------------------
// Launch
// ---------------------------------------------------------------------------
extern "C" void kernel_launch(void* const* d_in, const int* in_sizes, int n_in,
                              void* d_out, int out_size) {
    const float* x       = (const float*)d_in[0];
    const float* wq      = (const float*)d_in[1];
    const float* wk      = (const float*)d_in[2];
    const float* wv      = (const float*)d_in[3];
    const float* wo      = (const float*)d_in[4];
    const float* norm1_w = (const float*)d_in[5];
    const float* norm2_w = (const float*)d_in[6];
    const float* w_in    = (const float*)d_in[7];
    const float* w_out   = (const float*)d_in[8];
    float* out = (float*)d_out;

    bf16 *xrh, *xrl, *xh, *xl, *qh, *ql, *kh, *kl, *vh, *vl, *ctxh, *ctxl;
    bf16 *hh, *hl, *acth, *actl;
    bf16 *wqh, *wql, *wkh, *wkl, *wvh, *wvl, *woh, *wol, *wih, *wil, *wuh, *wul;
    float *attn, *h, *fc;
    cudaGetSymbolAddress((void**)&xrh,  g_xrot_hi);
    cudaGetSymbolAddress((void**)&xrl,  g_xrot_lo);
    cudaGetSymbolAddress((void**)&xh,   g_x_hi);
    cudaGetSymbolAddress((void**)&xl,   g_x_lo);
    cudaGetSymbolAddress((void**)&qh,   g_q_hi);
    cudaGetSymbolAddress((void**)&ql,   g_q_lo);
    cudaGetSymbolAddress((void**)&kh,   g_k_hi);
    cudaGetSymbolAddress((void**)&kl,   g_k_lo);
    cudaGetSymbolAddress((void**)&vh,   g_v_hi);
    cudaGetSymbolAddress((void**)&vl,   g_v_lo);
    cudaGetSymbolAddress((void**)&ctxh, g_ctx_hi);
    cudaGetSymbolAddress((void**)&ctxl, g_ctx_lo);
    cudaGetSymbolAddress((void**)&attn, g_attn);
    cudaGetSymbolAddress((void**)&h,    g_h);
    cudaGetSymbolAddress((void**)&hh,   g_h_hi);
    cudaGetSymbolAddress((void**)&hl,   g_h_lo);
    cudaGetSymbolAddress((void**)&acth, g_act_hi);
    cudaGetSymbolAddress((void**)&actl, g_act_lo);
    cudaGetSymbolAddress((void**)&fc,   g_fc);
    cudaGetSymbolAddress((void**)&wqh,  g_wqT_hi);
    cudaGetSymbolAddress((void**)&wql,  g_wqT_lo);
    cudaGetSymbolAddress((void**)&wkh,  g_wkT_hi);
    cudaGetSymbolAddress((void**)&wkl,  g_wkT_lo);
    cudaGetSymbolAddress((void**)&wvh,  g_wvT_hi);
    cudaGetSymbolAddress((void**)&wvl,  g_wvT_lo);
    cudaGetSymbolAddress((void**)&woh,  g_woT_hi);
    cudaGetSymbolAddress((void**)&wol,  g_woT_lo);
    cudaGetSymbolAddress((void**)&wih,  g_winT_hi);
    cudaGetSymbolAddress((void**)&wil,  g_winT_lo);
    cudaGetSymbolAddress((void**)&wuh,  g_woutT_hi);
    cudaGetSymbolAddress((void**)&wul,  g_woutT_lo);

    cudaFuncSetAttribute(mma_gemm, cudaFuncAttributeMaxDynamicSharedMemorySize,
                         MG_SMEM);
    cudaFuncSetAttribute(flash_mma_kernel, cudaFuncAttributeMaxDynamicSharedMemorySize,
                         FL_SMEM);

    // 0. Transpose + split weights -> [N][K] bf16 hi/lo (w_in interleaved a/g)
    transpose_split_kernel<<<dim3(EMB/32,   EMB/32), 256>>>(wq,    wqh, wql, EMB, EMB, 0);
    transpose_split_kernel<<<dim3(KVW/32,   EMB/32), 256>>>(wk,    wkh, wkl, EMB, KVW, 0);
    transpose_split_kernel<<<dim3(KVW/32,   EMB/32), 256>>>(wv,    wvh, wvl, EMB, KVW, 0);
    transpose_split_kernel<<<dim3(EMB/32,   EMB/32), 256>>>(wo,    woh, wol, EMB, EMB, 0);
    transpose_split_kernel<<<dim3(2*FFN/32, EMB/32), 256>>>(w_in,  wih, wil, EMB, 2*FFN, FFN);
    transpose_split_kernel<<<dim3(EMB/32,   FFN/32), 256>>>(w_out, wuh, wul, FFN, EMB, 0);

    // 1. RoPE (+split) and split(x)
    rope_split_kernel<<<(TOK * EMB + 255) / 256, 256>>>(x, xrh, xrl);
    split_kernel<<<(TOK * EMB + 255) / 256, 256>>>(x, xh, xl, (size_t)TOK * EMB);

    // 2-4. Q/K/V projections -> bf16 hi/lo outputs
    mma_gemm<<<dim3(TOK/128, EMB/128), 256, MG_SMEM>>>(xrh, xrl, wqh, wql,
        nullptr, qh, ql, TOK, EMB, EMB, 1);
    mma_gemm<<<dim3(TOK/128, KVW/128), 256, MG_SMEM>>>(xrh, xrl, wkh, wkl,
        nullptr, kh, kl, TOK, KVW, EMB, 1);
    mma_gemm<<<dim3(TOK/128, KVW/128), 256, MG_SMEM>>>(xh,  xl,  wvh, wvl,
        nullptr, vh, vl, TOK, KVW, EMB, 1);

    // 5. Tensor-core flash attention -> ctx hi/lo
    flash_mma_kernel<<<dim3(SEQ/128, NHEAD, BATCH), 256, FL_SMEM>>>(
        qh, ql, kh, kl, vh, vl, ctxh, ctxl);

    // 6. Output projection (fp32 out)
    mma_gemm<<<dim3(TOK/128, EMB/128), 256, MG_SMEM>>>(ctxh, ctxl, woh, wol,
        attn, nullptr, nullptr, TOK, EMB, EMB, 0);

    // 7. h = rmsnorm(x + attn) * norm1_w  (+ split)
    add_rmsnorm_kernel<<<TOK, 256>>>(x, attn, norm1_w, h, hh, hl);

    // 8+9. act = geglu(h @ w_in) fused -> bf16 hi/lo  (w_in cols interleaved)
    mma_gemm<<<dim3(TOK/128, 2*FFN/128), 256, MG_SMEM>>>(hh, hl, wih, wil,
        nullptr, acth, actl, TOK, 2*FFN, EMB, 2);

    // 10. fc = act @ w_out (fp32 out)
    mma_gemm<<<dim3(TOK/128, EMB/128), 256, MG_SMEM>>>(acth, actl, wuh, wul,
        fc, nullptr, nullptr, TOK, EMB, FFN, 0);

    // 11. out = rmsnorm(h + fc) * norm2_w
    add_rmsnorm_kernel<<<TOK, 256>>>(h, fc, norm2_w, out, nullptr, nullptr);
}

// round 11
// speedup vs baseline: 1.1697x; 1.1697x over previous
#include <cuda_runtime.h>
#include <cuda_bf16.h>
#include <math.h>
#include <stdint.h>

// Problem constants
#define BATCH 2
#define SEQ   2048
#define EMB   2048
#define NHEAD 16
#define NGRP  4
#define HDIM  128
#define FFN   8192
#define TOK   (BATCH*SEQ)          // 4096 rows
#define KVW   (NGRP*HDIM)          // 512

typedef __nv_bfloat16 bf16;

// ---------------------------------------------------------------------------
// PTX helpers (portable sm_80+: cp.async / ldmatrix / mma.sync)
// ---------------------------------------------------------------------------
__device__ __forceinline__ uint32_t smem_to_u32(const void* smem_ptr) {
    uint32_t addr;
    asm("{ .reg .u64 tmp; cvta.to.shared.u64 tmp, %1; cvt.u32.u64 %0, tmp; }"
        : "=r"(addr) : "l"(smem_ptr));
    return addr;
}

#define CP_ASYNC16(dst, src) \
    asm volatile("cp.async.cg.shared.global [%0], [%1], 16;\n" \
                 :: "r"(dst), "l"(src))
#define CP_COMMIT() asm volatile("cp.async.commit_group;\n" ::: "memory")
#define CP_WAIT(N)  asm volatile("cp.async.wait_group %0;\n" :: "n"(N) : "memory")

__device__ __forceinline__ void ldsm_x4(uint32_t* r, uint32_t addr) {
    asm volatile("ldmatrix.sync.aligned.m8n8.x4.shared.b16 {%0,%1,%2,%3}, [%4];\n"
        : "=r"(r[0]), "=r"(r[1]), "=r"(r[2]), "=r"(r[3]) : "r"(addr));
}

__device__ __forceinline__ void ldsm_x4_t(uint32_t* r, uint32_t addr) {
    asm volatile("ldmatrix.sync.aligned.m8n8.x4.trans.shared.b16 {%0,%1,%2,%3}, [%4];\n"
        : "=r"(r[0]), "=r"(r[1]), "=r"(r[2]), "=r"(r[3]) : "r"(addr));
}

__device__ __forceinline__ void mma_bf16(float* c, const uint32_t* a, const uint32_t* b) {
    asm volatile(
        "mma.sync.aligned.m16n8k16.row.col.f32.bf16.bf16.f32 "
        "{%0,%1,%2,%3}, {%4,%5,%6,%7}, {%8,%9}, {%0,%1,%2,%3};\n"
        : "+f"(c[0]), "+f"(c[1]), "+f"(c[2]), "+f"(c[3])
        : "r"(a[0]), "r"(a[1]), "r"(a[2]), "r"(a[3]), "r"(b[0]), "r"(b[1]));
}

__device__ __forceinline__ void split2(float v, bf16& h, bf16& l) {
    h = __float2bfloat16(v);
    l = __float2bfloat16(v - __bfloat162float(h));
}

// pack float pair -> (hi bf162, lo bf162) as uint32
__device__ __forceinline__ void split_pair(float a, float b, uint32_t& hu, uint32_t& lu) {
    __nv_bfloat162 h = __float22bfloat162_rn(make_float2(a, b));
    float2 back = __bfloat1622float2(h);
    __nv_bfloat162 l = __float22bfloat162_rn(make_float2(a - back.x, b - back.y));
    hu = *reinterpret_cast<uint32_t*>(&h);
    lu = *reinterpret_cast<uint32_t*>(&l);
}

__device__ __forceinline__ float gelu_exact(float a) {
    return 0.5f * a * (1.0f + erff(a * 0.70710678118654752f));
}

// ---------------------------------------------------------------------------
// Scratch (device globals; allocation-free per harness rules)
// ---------------------------------------------------------------------------
__device__ __align__(256) bf16 g_xrot_hi[TOK*EMB];
__device__ __align__(256) bf16 g_xrot_lo[TOK*EMB];
__device__ __align__(256) bf16 g_x_hi[TOK*EMB];
__device__ __align__(256) bf16 g_x_lo[TOK*EMB];
__device__ __align__(256) bf16 g_q_hi[TOK*EMB];
__device__ __align__(256) bf16 g_q_lo[TOK*EMB];
__device__ __align__(256) bf16 g_k_hi[TOK*KVW];
__device__ __align__(256) bf16 g_k_lo[TOK*KVW];
__device__ __align__(256) bf16 g_v_hi[TOK*KVW];
__device__ __align__(256) bf16 g_v_lo[TOK*KVW];
__device__ __align__(256) bf16 g_ctx_hi[TOK*EMB];
__device__ __align__(256) bf16 g_ctx_lo[TOK*EMB];
__device__ __align__(256) float g_attn[TOK*EMB];
__device__ __align__(256) float g_h[TOK*EMB];
__device__ __align__(256) bf16 g_h_hi[TOK*EMB];
__device__ __align__(256) bf16 g_h_lo[TOK*EMB];
__device__ __align__(256) bf16 g_act_hi[(size_t)TOK*FFN];
__device__ __align__(256) bf16 g_act_lo[(size_t)TOK*FFN];
__device__ __align__(256) float g_fc[TOK*EMB];
// transposed weights (B^T layout [N][K]), split
__device__ __align__(256) bf16 g_wqT_hi[EMB*EMB];
__device__ __align__(256) bf16 g_wqT_lo[EMB*EMB];
__device__ __align__(256) bf16 g_wkT_hi[KVW*EMB];
__device__ __align__(256) bf16 g_wkT_lo[KVW*EMB];
__device__ __align__(256) bf16 g_wvT_hi[KVW*EMB];
__device__ __align__(256) bf16 g_wvT_lo[KVW*EMB];
__device__ __align__(256) bf16 g_woT_hi[EMB*EMB];
__device__ __align__(256) bf16 g_woT_lo[EMB*EMB];
__device__ __align__(256) bf16 g_winT_hi[(size_t)2*FFN*EMB];
__device__ __align__(256) bf16 g_winT_lo[(size_t)2*FFN*EMB];
__device__ __align__(256) bf16 g_woutT_hi[(size_t)EMB*FFN];
__device__ __align__(256) bf16 g_woutT_lo[(size_t)EMB*FFN];

// ---------------------------------------------------------------------------
// Transpose + split; optional row-interleave for GeGLU pairing:
// ilv_half>0 -> out row r' = (r < ilv_half) ? 2r : 2(r-ilv_half)+1
// ---------------------------------------------------------------------------
__global__ __launch_bounds__(256) void transpose_split_kernel(
        const float* __restrict__ in, bf16* __restrict__ hi, bf16* __restrict__ lo,
        int R, int C, int ilv_half) {
    __shared__ float t[32][33];
    int bx = blockIdx.x * 32, by = blockIdx.y * 32;
    int tx = threadIdx.x & 31, ty = threadIdx.x >> 5;
    #pragma unroll
    for (int i = ty; i < 32; i += 8)
        t[i][tx] = in[(size_t)(by + i) * C + bx + tx];
    __syncthreads();
    #pragma unroll
    for (int i = ty; i < 32; i += 8) {
        float v = t[tx][i];
        bf16 h, l; split2(v, h, l);
        size_t r = (size_t)(bx + i);
        if (ilv_half) r = (r < (size_t)ilv_half) ? 2*r : 2*(r - ilv_half) + 1;
        size_t o = r * R + by + tx;
        hi[o] = h; lo[o] = l;
    }
}

__global__ __launch_bounds__(256) void split_kernel(const float* __restrict__ in,
                                                    bf16* __restrict__ hi,
                                                    bf16* __restrict__ lo, size_t n) {
    size_t idx = (size_t)blockIdx.x * 256 + threadIdx.x;
    if (idx >= n) return;
    bf16 h, l; split2(in[idx], h, l);
    hi[idx] = h; lo[idx] = l;
}

// ---------------------------------------------------------------------------
// RoPE -> split bf16 pair
// ---------------------------------------------------------------------------
__global__ __launch_bounds__(256) void rope_split_kernel(const float* __restrict__ x,
                                                         bf16* __restrict__ hi,
                                                         bf16* __restrict__ lo) {
    int idx = blockIdx.x * 256 + threadIdx.x;
    if (idx >= TOK*EMB) return;
    int t = idx / EMB;
    int e = idx % EMB;
    int n = t % SEQ;
    int d = e % HDIM;
    int j; float partner; float sign;
    if (d < 64) { j = d;      partner = x[idx + 64]; sign = -1.f; }
    else        { j = d - 64; partner = x[idx - 64]; sign =  1.f; }
    float invf = powf(10000.0f, -(float)j / 64.0f);
    float ang = (float)n * invf;
    float c = cosf(ang), s = sinf(ang);
    float v = x[idx] * c + sign * partner * s;
    bf16 h, l; split2(v, h, l);
    hi[idx] = h; lo[idx] = l;
}

// ---------------------------------------------------------------------------
// bf16-split tensor-core GEMM: C = A @ BT^T.  128x128 tile, Kstep 32, 8 warps,
// 2-stage cp.async, TWO CTAs per SM (launch_bounds cap 128 regs).
// Inner loop B-resident, A streamed per-mt to fit the register budget.
// mode: 0 = fp32 C; 1 = bf16 hi/lo split; 2 = GeGLU epilogue width N/2.
// ---------------------------------------------------------------------------
#define WST_B    80
#define OP_BYTES (128*WST_B)
#define STAGE_B  (4*OP_BYTES)
#define MG_SMEM  (2*STAGE_B)     // 81920 per CTA -> 2 CTAs/SM

__global__ __launch_bounds__(256, 2) void mma_gemm(
        const bf16* __restrict__ Ahi, const bf16* __restrict__ Alo,
        const bf16* __restrict__ Bhi, const bf16* __restrict__ Blo,
        float* __restrict__ C, bf16* __restrict__ Ch, bf16* __restrict__ Cl,
        int M, int N, int K, int mode) {
    extern __shared__ char smem[];
    const uint32_t sb = smem_to_u32(smem);
    const int tid = threadIdx.x;
    const int m0 = blockIdx.x * 128, n0 = blockIdx.y * 128;
    const int warp = tid >> 5, lane = tid & 31;
    const int wm = warp & 1, wn = warp >> 1;

    const bf16* srcs[4] = { Ahi + (size_t)m0 * K, Alo + (size_t)m0 * K,
                            Bhi + (size_t)n0 * K, Blo + (size_t)n0 * K };

    float acc[4][4][4];
    #pragma unroll
    for (int i = 0; i < 4; i++)
        #pragma unroll
        for (int j = 0; j < 4; j++)
            #pragma unroll
            for (int r = 0; r < 4; r++) acc[i][j][r] = 0.f;

    const int S = K >> 5;
    const int lA_row = lane & 15, lA_k = lane >> 4;
    const int lB_row = ((lane >> 4) << 3) + (lane & 7);
    const int lB_k = (lane >> 3) & 1;

    // stage loader: stage s -> buffer s%2
    auto issue_stage = [&](int s) {
        const uint32_t bufb = sb + (uint32_t)(s & 1) * STAGE_B;
        const int k0 = s << 5;
        #pragma unroll
        for (int it = 0; it < 8; it++) {
            int idx = tid + (it << 8);
            int op = it >> 1;
            int j = idx & 511;
            int row = j >> 2, ch = j & 3;
            const bf16* src = srcs[op] + (size_t)row * K + k0 + ch * 8;
            uint32_t dst = bufb + (uint32_t)(op * OP_BYTES + row * WST_B + ch * 16);
            CP_ASYNC16(dst, src);
        }
    };

    issue_stage(0); CP_COMMIT();

    for (int s = 0; s < S; s++) {
        if (s + 1 < S) {
            issue_stage(s + 1);
            CP_COMMIT();
            CP_WAIT(1);
        } else {
            CP_WAIT(0);
        }
        __syncthreads();

        const uint32_t base = sb + (uint32_t)(s & 1) * STAGE_B;
        #pragma unroll
        for (int k16 = 0; k16 < 2; k16++) {
            // B fragments resident (16 regs)
            uint32_t bh[4][2], bl[4][2];
            #pragma unroll
            for (int np = 0; np < 2; np++) {
                uint32_t rb = base + 2 * OP_BYTES
                            + (uint32_t)((wn * 32 + np * 16 + lB_row) * WST_B)
                            + k16 * 32 + lB_k * 16;
                uint32_t t4[4];
                ldsm_x4(t4, rb);
                bh[np*2][0] = t4[0]; bh[np*2][1] = t4[1];
                bh[np*2+1][0] = t4[2]; bh[np*2+1][1] = t4[3];
                ldsm_x4(t4, rb + OP_BYTES);
                bl[np*2][0] = t4[0]; bl[np*2][1] = t4[1];
                bl[np*2+1][0] = t4[2]; bl[np*2+1][1] = t4[3];
            }
            // A streamed per-mt (8 regs transient)
            #pragma unroll
            for (int mt = 0; mt < 4; mt++) {
                uint32_t ah[4], al[4];
                uint32_t ra = base + (uint32_t)((wm * 64 + mt * 16 + lA_row) * WST_B)
                            + k16 * 32 + lA_k * 16;
                ldsm_x4(ah, ra);
                ldsm_x4(al, ra + OP_BYTES);
                #pragma unroll
                for (int nt = 0; nt < 4; nt++) {
                    mma_bf16(acc[mt][nt], ah, bh[nt]);
                    mma_bf16(acc[mt][nt], ah, bl[nt]);
                    mma_bf16(acc[mt][nt], al, bh[nt]);
                }
            }
        }
        __syncthreads();   // all warps done with buffer s&1 before refill
    }

    #pragma unroll
    for (int mt = 0; mt < 4; mt++) {
        int m = m0 + wm * 64 + mt * 16 + (lane >> 2);
        #pragma unroll
        for (int nt = 0; nt < 4; nt++) {
            int n = n0 + wn * 32 + nt * 8 + 2 * (lane & 3);
            if (mode == 0) {
                *(float2*)(C + (size_t)m * N + n) =
                    make_float2(acc[mt][nt][0], acc[mt][nt][1]);
                *(float2*)(C + (size_t)(m + 8) * N + n) =
                    make_float2(acc[mt][nt][2], acc[mt][nt][3]);
            } else if (mode == 1) {
                uint32_t hu, lu;
                split_pair(acc[mt][nt][0], acc[mt][nt][1], hu, lu);
                *(uint32_t*)(Ch + (size_t)m * N + n) = hu;
                *(uint32_t*)(Cl + (size_t)m * N + n) = lu;
                split_pair(acc[mt][nt][2], acc[mt][nt][3], hu, lu);
                *(uint32_t*)(Ch + (size_t)(m + 8) * N + n) = hu;
                *(uint32_t*)(Cl + (size_t)(m + 8) * N + n) = lu;
            } else {
                // GeGLU: (c0,c1)=(a,g) for row m; (c2,c3) for row m+8
                int Nh = N >> 1;
                int f = n >> 1;
                float v0 = gelu_exact(acc[mt][nt][0]) * acc[mt][nt][1];
                float v1 = gelu_exact(acc[mt][nt][2]) * acc[mt][nt][3];
                bf16 h0, l0, h1, l1;
                split2(v0, h0, l0);
                split2(v1, h1, l1);
                Ch[(size_t)m * Nh + f] = h0;       Cl[(size_t)m * Nh + f] = l0;
                Ch[(size_t)(m + 8) * Nh + f] = h1; Cl[(size_t)(m + 8) * Nh + f] = l1;
            }
        }
    }
}

// ---------------------------------------------------------------------------
// Tensor-core flash attention (bf16 split, causal, GQA)
// CTA: 128 q-rows, iterate 64-kv tiles.  8 warps, warp = 16 q-rows x all 64 kv.
// Q [128][272B] hi/lo resident; K,V [64][272B] hi/lo, 2-stage cp.async ring.
// V stored row-major [kv][d]; P@V B-operands via ldmatrix.trans.
// ---------------------------------------------------------------------------
#define FSQ_H  0
#define FSQ_L  34816
#define FST0   69632
#define FSTAGE 69632          // per-stage: KH,KL,VH,VL each 64*272=17408
#define FKL_OFF 17408
#define FVH_OFF 34816
#define FVL_OFF 52224
#define FL_SMEM (FST0 + 2*FSTAGE)   // 208896

__global__ __launch_bounds__(256) void flash_mma_kernel(
        const bf16* __restrict__ Qh, const bf16* __restrict__ Ql,
        const bf16* __restrict__ Kh, const bf16* __restrict__ Kl,
        const bf16* __restrict__ Vh, const bf16* __restrict__ Vl,
        bf16* __restrict__ Oh, bf16* __restrict__ Ol) {
    extern __shared__ char smem[];
    const uint32_t sb = smem_to_u32(smem);
    const int qt = (int)gridDim.x - 1 - (int)blockIdx.x;  // big tiles first
    const int hd = blockIdx.y, b = blockIdx.z;
    const int g = hd / (NHEAD / NGRP);
    const int tid = threadIdx.x;
    const int warp = tid >> 5, lane = tid & 31;
    const int lA_row = lane & 15, lA_k = lane >> 4;
    const int lB_row = ((lane >> 4) << 3) + (lane & 7);
    const int lB_k = (lane >> 3) & 1;
    const float SC = 0.08838834764831845f * 1.4426950408889634f;  // scale*log2e

    // load Q tile (128 x 128 bf16, hi+lo) — plain vector stores, synced below
    {
        const size_t qbase = ((size_t)(b * SEQ + qt * 128)) * EMB + hd * HDIM;
        #pragma unroll
        for (int it = 0; it < 8; it++) {
            int i = tid + (it << 8);       // 0..2047
            int row = i >> 4, ch = i & 15;
            size_t ga = qbase + (size_t)row * EMB + ch * 8;
            *(uint4*)(smem + FSQ_H + row * 272 + ch * 16) = *(const uint4*)(Qh + ga);
            *(uint4*)(smem + FSQ_L + row * 272 + ch * 16) = *(const uint4*)(Ql + ga);
        }
    }

    // K/V stage loader (cp.async, 16 chunks per thread)
    auto issue_kv = [&](int kt) {
        const uint32_t stb = sb + FST0 + (uint32_t)(kt & 1) * FSTAGE;
        const size_t kbase = ((size_t)(b * SEQ + kt * 64)) * KVW + g * HDIM;
        const bf16* gsrc[4] = { Kh + kbase, Kl + kbase, Vh + kbase, Vl + kbase };
        #pragma unroll
        for (int it = 0; it < 16; it++) {
            int idx = tid + (it << 8);
            int arr = it >> 2;              // 1024 chunks per array
            int j = idx & 1023;
            int row = j >> 4, ch = j & 15;
            const bf16* src = gsrc[arr] + (size_t)row * KVW + ch * 8;
            uint32_t dst = stb + (uint32_t)arr * 17408u + (uint32_t)(row * 272 + ch * 16);
            CP_ASYNC16(dst, src);
        }
    };

    float o[16][4];
    #pragma unroll
    for (int i = 0; i < 16; i++)
        #pragma unroll
        for (int r = 0; r < 4; r++) o[i][r] = 0.f;
    float m0 = -1e30f, m1 = -1e30f, l0 = 0.f, l1 = 0.f;

    const int qg0 = qt * 128 + warp * 16 + (lane >> 2);
    const int qg1 = qg0 + 8;
    const int NT = 2 * qt + 2;

    issue_kv(0);
    CP_COMMIT();

    for (int kt = 0; kt < NT; kt++) {
        if (kt + 1 < NT) {
            issue_kv(kt + 1);   // writes buf (kt+1)&1, last read at kt-1 (synced)
            CP_COMMIT();
            CP_WAIT(1);
        } else {
            CP_WAIT(0);
        }
        __syncthreads();
        const uint32_t stb = sb + FST0 + (uint32_t)(kt & 1) * FSTAGE;

        // --- S = Q @ K^T (3-MMA split) ---
        float s[8][4];
        #pragma unroll
        for (int j = 0; j < 8; j++)
            #pragma unroll
            for (int r = 0; r < 4; r++) s[j][r] = 0.f;

        #pragma unroll
        for (int ks = 0; ks < 8; ks++) {
            uint32_t qh4[4], ql4[4];
            uint32_t ra = sb + FSQ_H + (uint32_t)((warp * 16 + lA_row) * 272)
                        + ks * 32 + lA_k * 16;
            ldsm_x4(qh4, ra);
            ldsm_x4(ql4, ra + (FSQ_L - FSQ_H));
            #pragma unroll
            for (int np = 0; np < 4; np++) {
                uint32_t th[4], tl[4];
                uint32_t rb = stb + (uint32_t)((np * 16 + lB_row) * 272)
                            + ks * 32 + lB_k * 16;
                ldsm_x4(th, rb);
                ldsm_x4(tl, rb + FKL_OFF);
                uint32_t bh0[2] = {th[0], th[1]}, bh1[2] = {th[2], th[3]};
                uint32_t bl0[2] = {tl[0], tl[1]}, bl1[2] = {tl[2], tl[3]};
                mma_bf16(s[2*np],   qh4, bh0);
                mma_bf16(s[2*np],   qh4, bl0);
                mma_bf16(s[2*np],   ql4, bh0);
                mma_bf16(s[2*np+1], qh4, bh1);
                mma_bf16(s[2*np+1], qh4, bl1);
                mma_bf16(s[2*np+1], ql4, bh1);
            }
        }

        // --- online softmax (raw-score max; mask by zeroing p) ---
        float tm0 = -1e30f, tm1 = -1e30f;
        #pragma unroll
        for (int j = 0; j < 8; j++) {
            tm0 = fmaxf(tm0, fmaxf(s[j][0], s[j][1]));
            tm1 = fmaxf(tm1, fmaxf(s[j][2], s[j][3]));
        }
        tm0 = fmaxf(tm0, __shfl_xor_sync(0xffffffffu, tm0, 1));
        tm0 = fmaxf(tm0, __shfl_xor_sync(0xffffffffu, tm0, 2));
        tm1 = fmaxf(tm1, __shfl_xor_sync(0xffffffffu, tm1, 1));
        tm1 = fmaxf(tm1, __shfl_xor_sync(0xffffffffu, tm1, 2));
        float m0n = fmaxf(m0, tm0), m1n = fmaxf(m1, tm1);
        float c0 = exp2f((m0 - m0n) * SC), c1 = exp2f((m1 - m1n) * SC);

        const bool domask = (kt >= 2 * qt);
        float l0a = 0.f, l1a = 0.f;
        #pragma unroll
        for (int j = 0; j < 8; j++) {
            float p0 = exp2f((s[j][0] - m0n) * SC);
            float p1 = exp2f((s[j][1] - m0n) * SC);
            float p2 = exp2f((s[j][2] - m1n) * SC);
            float p3 = exp2f((s[j][3] - m1n) * SC);
            if (domask) {
                int colb = kt * 64 + j * 8 + 2 * (lane & 3);
                if (colb     > qg0) p0 = 0.f;
                if (colb + 1 > qg0) p1 = 0.f;
                if (colb     > qg1) p2 = 0.f;
                if (colb + 1 > qg1) p3 = 0.f;
            }
            s[j][0] = p0; s[j][1] = p1; s[j][2] = p2; s[j][3] = p3;
            l0a += p0 + p1; l1a += p2 + p3;
        }
        l0a += __shfl_xor_sync(0xffffffffu, l0a, 1);
        l0a += __shfl_xor_sync(0xffffffffu, l0a, 2);
        l1a += __shfl_xor_sync(0xffffffffu, l1a, 1);
        l1a += __shfl_xor_sync(0xffffffffu, l1a, 2);
        l0 = l0 * c0 + l0a;
        l1 = l1 * c1 + l1a;
        m0 = m0n; m1 = m1n;

        #pragma unroll
        for (int i = 0; i < 16; i++) {
            o[i][0] *= c0; o[i][1] *= c0; o[i][2] *= c1; o[i][3] *= c1;
        }

        // --- O += P @ V (3-MMA split; V [kv][d] via ldmatrix.trans) ---
        #pragma unroll
        for (int ks = 0; ks < 4; ks++) {
            uint32_t ah[4], al[4];
            split_pair(s[2*ks][0],   s[2*ks][1],   ah[0], al[0]);
            split_pair(s[2*ks][2],   s[2*ks][3],   ah[1], al[1]);
            split_pair(s[2*ks+1][0], s[2*ks+1][1], ah[2], al[2]);
            split_pair(s[2*ks+1][2], s[2*ks+1][3], ah[3], al[3]);
            #pragma unroll
            for (int dp = 0; dp < 8; dp++) {
                uint32_t th[4], tl[4];
                uint32_t rb = stb + FVH_OFF
                            + (uint32_t)((ks * 16 + (lane & 15)) * 272)
                            + (uint32_t)((dp * 16 + ((lane >> 4) << 3)) * 2);
                ldsm_x4_t(th, rb);
                ldsm_x4_t(tl, rb + (FVL_OFF - FVH_OFF));
                uint32_t bh0[2] = {th[0], th[1]}, bh1[2] = {th[2], th[3]};
                uint32_t bl0[2] = {tl[0], tl[1]}, bl1[2] = {tl[2], tl[3]};
                mma_bf16(o[2*dp],   ah, bh0);
                mma_bf16(o[2*dp],   ah, bl0);
                mma_bf16(o[2*dp],   al, bh0);
                mma_bf16(o[2*dp+1], ah, bh1);
                mma_bf16(o[2*dp+1], ah, bl1);
                mma_bf16(o[2*dp+1], al, bh1);
            }
        }
        __syncthreads();   // all warps done reading stage kt&1 before overwrite
    }

    // epilogue: divide by l, write ctx hi/lo
    float inv0 = 1.f / l0, inv1 = 1.f / l1;
    const size_t tok0 = (size_t)(b * SEQ + qt * 128 + warp * 16 + (lane >> 2));
    #pragma unroll
    for (int dt = 0; dt < 16; dt++) {
        int col = hd * HDIM + dt * 8 + 2 * (lane & 3);
        uint32_t hu, lu;
        split_pair(o[dt][0] * inv0, o[dt][1] * inv0, hu, lu);
        *(uint32_t*)(Oh + tok0 * EMB + col) = hu;
        *(uint32_t*)(Ol + tok0 * EMB + col) = lu;
        split_pair(o[dt][2] * inv1, o[dt][3] * inv1, hu, lu);
        *(uint32_t*)(Oh + (tok0 + 8) * EMB + col) = hu;
        *(uint32_t*)(Ol + (tok0 + 8) * EMB + col) = lu;
    }
}

// ---------------------------------------------------------------------------
// out = rmsnorm(a + b) * w ; optional split outputs
// ---------------------------------------------------------------------------
__global__ __launch_bounds__(256) void add_rmsnorm_kernel(const float* __restrict__ a,
                                                          const float* __restrict__ b,
                                                          const float* __restrict__ w,
                                                          float* __restrict__ out,
                                                          bf16* __restrict__ oh,
                                                          bf16* __restrict__ ol) {
    int row = blockIdx.x;
    const float4* a4 = (const float4*)(a + (size_t)row * EMB);
    const float4* b4 = (const float4*)(b + (size_t)row * EMB);
    const float4* w4 = (const float4*)w;
    float4* o4 = (float4*)(out + (size_t)row * EMB);

    float4 s[2];
    float ss = 0.f;
    #pragma unroll
    for (int i = 0; i < 2; i++) {
        float4 av = a4[threadIdx.x + i * 256];
        float4 bv = b4[threadIdx.x + i * 256];
        s[i] = make_float4(av.x + bv.x, av.y + bv.y, av.z + bv.z, av.w + bv.w);
        ss += s[i].x * s[i].x + s[i].y * s[i].y + s[i].z * s[i].z + s[i].w * s[i].w;
    }
    __shared__ float red[8];
    for (int o = 16; o > 0; o >>= 1) ss += __shfl_xor_sync(0xffffffff, ss, o);
    if ((threadIdx.x & 31) == 0) red[threadIdx.x >> 5] = ss;
    __syncthreads();
    __shared__ float total_s;
    if (threadIdx.x == 0) {
        float t = 0.f;
        #pragma unroll
        for (int i = 0; i < 8; i++) t += red[i];
        total_s = t;
    }
    __syncthreads();
    float rstd = rsqrtf(total_s / (float)EMB + 1e-6f);
    #pragma unroll
    for (int i = 0; i < 2; i++) {
        float4 wv = w4[threadIdx.x + i * 256];
        float4 ov = make_float4(s[i].x * rstd * wv.x, s[i].y * rstd * wv.y,
                                s[i].z * rstd * wv.z, s[i].w * rstd * wv.w);
        o4[threadIdx.x + i * 256] = ov;
        if (oh) {
            size_t base = (size_t)row * EMB + (threadIdx.x + i * 256) * 4;
            uint32_t hu, lu;
            split_pair(ov.x, ov.y, hu, lu);
            *(uint32_t*)(oh + base) = hu; *(uint32_t*)(ol + base) = lu;
            split_pair(ov.z, ov.w, hu, lu);
            *(uint32_t*)(oh + base + 2) = hu; *(uint32_t*)(ol + base + 2) = lu;
        }
    }
}

// ---------------------------------------------------------------------------
// Launch
// ---------------------------------------------------------------------------
extern "C" void kernel_launch(void* const* d_in, const int* in_sizes, int n_in,
                              void* d_out, int out_size) {
    const float* x       = (const float*)d_in[0];
    const float* wq      = (const float*)d_in[1];
    const float* wk      = (const float*)d_in[2];
    const float* wv      = (const float*)d_in[3];
    const float* wo      = (const float*)d_in[4];
    const float* norm1_w = (const float*)d_in[5];
    const float* norm2_w = (const float*)d_in[6];
    const float* w_in    = (const float*)d_in[7];
    const float* w_out   = (const float*)d_in[8];
    float* out = (float*)d_out;

    bf16 *xrh, *xrl, *xh, *xl, *qh, *ql, *kh, *kl, *vh, *vl, *ctxh, *ctxl;
    bf16 *hh, *hl, *acth, *actl;
    bf16 *wqh, *wql, *wkh, *wkl, *wvh, *wvl, *woh, *wol, *wih, *wil, *wuh, *wul;
    float *attn, *h, *fc;
    cudaGetSymbolAddress((void**)&xrh,  g_xrot_hi);
    cudaGetSymbolAddress((void**)&xrl,  g_xrot_lo);
    cudaGetSymbolAddress((void**)&xh,   g_x_hi);
    cudaGetSymbolAddress((void**)&xl,   g_x_lo);
    cudaGetSymbolAddress((void**)&qh,   g_q_hi);
    cudaGetSymbolAddress((void**)&ql,   g_q_lo);
    cudaGetSymbolAddress((void**)&kh,   g_k_hi);
    cudaGetSymbolAddress((void**)&kl,   g_k_lo);
    cudaGetSymbolAddress((void**)&vh,   g_v_hi);
    cudaGetSymbolAddress((void**)&vl,   g_v_lo);
    cudaGetSymbolAddress((void**)&ctxh, g_ctx_hi);
    cudaGetSymbolAddress((void**)&ctxl, g_ctx_lo);
    cudaGetSymbolAddress((void**)&attn, g_attn);
    cudaGetSymbolAddress((void**)&h,    g_h);
    cudaGetSymbolAddress((void**)&hh,   g_h_hi);
    cudaGetSymbolAddress((void**)&hl,   g_h_lo);
    cudaGetSymbolAddress((void**)&acth, g_act_hi);
    cudaGetSymbolAddress((void**)&actl, g_act_lo);
    cudaGetSymbolAddress((void**)&fc,   g_fc);
    cudaGetSymbolAddress((void**)&wqh,  g_wqT_hi);
    cudaGetSymbolAddress((void**)&wql,  g_wqT_lo);
    cudaGetSymbolAddress((void**)&wkh,  g_wkT_hi);
    cudaGetSymbolAddress((void**)&wkl,  g_wkT_lo);
    cudaGetSymbolAddress((void**)&wvh,  g_wvT_hi);
    cudaGetSymbolAddress((void**)&wvl,  g_wvT_lo);
    cudaGetSymbolAddress((void**)&woh,  g_woT_hi);
    cudaGetSymbolAddress((void**)&wol,  g_woT_lo);
    cudaGetSymbolAddress((void**)&wih,  g_winT_hi);
    cudaGetSymbolAddress((void**)&wil,  g_winT_lo);
    cudaGetSymbolAddress((void**)&wuh,  g_woutT_hi);
    cudaGetSymbolAddress((void**)&wul,  g_woutT_lo);

    cudaFuncSetAttribute(mma_gemm, cudaFuncAttributeMaxDynamicSharedMemorySize,
                         MG_SMEM);
    cudaFuncSetAttribute(flash_mma_kernel, cudaFuncAttributeMaxDynamicSharedMemorySize,
                         FL_SMEM);

    // 0. Transpose + split weights -> [N][K] bf16 hi/lo (w_in interleaved a/g)
    transpose_split_kernel<<<dim3(EMB/32,   EMB/32), 256>>>(wq,    wqh, wql, EMB, EMB, 0);
    transpose_split_kernel<<<dim3(KVW/32,   EMB/32), 256>>>(wk,    wkh, wkl, EMB, KVW, 0);
    transpose_split_kernel<<<dim3(KVW/32,   EMB/32), 256>>>(wv,    wvh, wvl, EMB, KVW, 0);
    transpose_split_kernel<<<dim3(EMB/32,   EMB/32), 256>>>(wo,    woh, wol, EMB, EMB, 0);
    transpose_split_kernel<<<dim3(2*FFN/32, EMB/32), 256>>>(w_in,  wih, wil, EMB, 2*FFN, FFN);
    transpose_split_kernel<<<dim3(EMB/32,   FFN/32), 256>>>(w_out, wuh, wul, FFN, EMB, 0);

    // 1. RoPE (+split) and split(x)
    rope_split_kernel<<<(TOK * EMB + 255) / 256, 256>>>(x, xrh, xrl);
    split_kernel<<<(TOK * EMB + 255) / 256, 256>>>(x, xh, xl, (size_t)TOK * EMB);

    // 2-4. Q/K/V projections -> bf16 hi/lo outputs
    mma_gemm<<<dim3(TOK/128, EMB/128), 256, MG_SMEM>>>(xrh, xrl, wqh, wql,
        nullptr, qh, ql, TOK, EMB, EMB, 1);
    mma_gemm<<<dim3(TOK/128, KVW/128), 256, MG_SMEM>>>(xrh, xrl, wkh, wkl,
        nullptr, kh, kl, TOK, KVW, EMB, 1);
    mma_gemm<<<dim3(TOK/128, KVW/128), 256, MG_SMEM>>>(xh,  xl,  wvh, wvl,
        nullptr, vh, vl, TOK, KVW, EMB, 1);

    // 5. Tensor-core flash attention -> ctx hi/lo
    flash_mma_kernel<<<dim3(SEQ/128, NHEAD, BATCH), 256, FL_SMEM>>>(
        qh, ql, kh, kl, vh, vl, ctxh, ctxl);

    // 6. Output projection (fp32 out)
    mma_gemm<<<dim3(TOK/128, EMB/128), 256, MG_SMEM>>>(ctxh, ctxl, woh, wol,
        attn, nullptr, nullptr, TOK, EMB, EMB, 0);

    // 7. h = rmsnorm(x + attn) * norm1_w  (+ split)
    add_rmsnorm_kernel<<<TOK, 256>>>(x, attn, norm1_w, h, hh, hl);

    // 8+9. act = geglu(h @ w_in) fused -> bf16 hi/lo  (w_in cols interleaved)
    mma_gemm<<<dim3(TOK/128, 2*FFN/128), 256, MG_SMEM>>>(hh, hl, wih, wil,
        nullptr, acth, actl, TOK, 2*FFN, EMB, 2);

    // 10. fc = act @ w_out (fp32 out)
    mma_gemm<<<dim3(TOK/128, EMB/128), 256, MG_SMEM>>>(acth, actl, wuh, wul,
        fc, nullptr, nullptr, TOK, EMB, FFN, 0);

    // 11. out = rmsnorm(h + fc) * norm2_w
    add_rmsnorm_kernel<<<TOK, 256>>>(h, fc, norm2_w, out, nullptr, nullptr);
}